// round 14
// baseline (speedup 1.0000x reference)
#include <cuda_runtime.h>
#include <cuda_bf16.h>

// out[b,t,c] = (x[b,src,c] + noise[b,src,c]*0.1f) * scale[b]
// src = (t - (shifts[b] - MAX_SHIFT)) mod T
// B=64, T=4096, C=128, fp32.
// Hint-axis probe: .cg loads (bypass L1 fill, default L2 aging) + .cs
// streaming store. 2x2 so far (sustained): none=61.50, ld.cs-only=63.71,
// st.cs-only=61.50, both.cs=59.87 (best). This tests whether the win is the
// L1-bypass component (then this matches/beats) or L2 evict-first (then ~61.5).

#define B_DIM 64
#define T_DIM 4096
#define C_DIM 128
#define MAX_SHIFT 409
#define NOISE_STD 0.1f

#define C4 (C_DIM / 4)   // 32 float4 per (b,t) row
#define THREADS 256

__global__ __launch_bounds__(THREADS)
void ts_augment_kernel(const float4* __restrict__ x,
                       const float4* __restrict__ noise,
                       const float*  __restrict__ scale,
                       const int*    __restrict__ shifts,
                       float4*       __restrict__ out)
{
    // flat index over B * T * C4 = 8,388,608; grid*block covers exactly.
    unsigned idx = blockIdx.x * blockDim.x + threadIdx.x;
    unsigned c4 = idx & (C4 - 1);            // idx % 32
    unsigned t  = (idx >> 5) & (T_DIM - 1);  // (idx / 32) % 4096
    unsigned b  = idx >> 17;                 // idx / (32*4096)

    int s = shifts[b] - MAX_SHIFT;           // [-409, 409]
    int src = (int)t - s;                    // [-409, 4504]
    if (src < 0)           src += T_DIM;
    else if (src >= T_DIM) src -= T_DIM;

    unsigned src_idx = (b << 17) + ((unsigned)src << 5) + c4;

    // .cg: cache-global loads — no L1 allocation, normal L2 policy.
    float4 xv = __ldcg(&x[src_idx]);
    float4 nv = __ldcg(&noise[src_idx]);

    float sc  = __ldg(&scale[b]);
    float nsc = sc * NOISE_STD;   // out = x*sc + n*(0.1*sc): independent MUL + FMA per lane

    float4 o;
    o.x = fmaf(nv.x, nsc, xv.x * sc);
    o.y = fmaf(nv.y, nsc, xv.y * sc);
    o.z = fmaf(nv.z, nsc, xv.z * sc);
    o.w = fmaf(nv.w, nsc, xv.w * sc);

    // Streaming store: keep the 128MB write stream out of L2.
    __stcs(&out[idx], o);
}

extern "C" void kernel_launch(void* const* d_in, const int* in_sizes, int n_in,
                              void* d_out, int out_size)
{
    const float4* x      = (const float4*)d_in[0];
    const float4* noise  = (const float4*)d_in[1];
    const float*  scale  = (const float*)d_in[2];
    const int*    shifts = (const int*)d_in[3];
    float4* out = (float4*)d_out;

    const unsigned total = B_DIM * T_DIM * C4;   // 8,388,608
    const unsigned blocks = total / THREADS;     // 32768

    ts_augment_kernel<<<blocks, THREADS>>>(x, noise, scale, shifts, out);
}

// round 15
// speedup vs baseline: 1.0288x; 1.0288x over previous
#include <cuda_runtime.h>
#include <cuda_bf16.h>

// out[b,t,c] = (x[b,src,c] + noise[b,src,c]*0.1f) * scale[b]
// src = (t - (shifts[b] - MAX_SHIFT)) mod T
// B=64, T=4096, C=128, fp32.
//
// FINAL kernel — measured-optimal configuration, reproduced 3x at
// 59.87-60.00 us sustained:
//   * float4 (128-bit) accesses          (v8 slower sustained: 61.95)
//   * 256-thread blocks                  (128/512 -> 61.09/61.50)
//   * ld.cs reads + st.cs store          (unique winner of 5-cell policy map:
//                                         none=61.50, ld-only=63.71,
//                                         st-only=61.50, cg+cs=61.63)
//   * hoisted per-batch scale, MUL+FMA per lane
// ~6.4 TB/s sustained on an irreducible 384 MB touch-once 2R:1W stream.

#define B_DIM 64
#define T_DIM 4096
#define C_DIM 128
#define MAX_SHIFT 409
#define NOISE_STD 0.1f

#define C4 (C_DIM / 4)   // 32 float4 per (b,t) row
#define THREADS 256

__global__ __launch_bounds__(THREADS)
void ts_augment_kernel(const float4* __restrict__ x,
                       const float4* __restrict__ noise,
                       const float*  __restrict__ scale,
                       const int*    __restrict__ shifts,
                       float4*       __restrict__ out)
{
    // flat index over B * T * C4 = 8,388,608; grid*block covers exactly.
    unsigned idx = blockIdx.x * blockDim.x + threadIdx.x;
    unsigned c4 = idx & (C4 - 1);            // idx % 32
    unsigned t  = (idx >> 5) & (T_DIM - 1);  // (idx / 32) % 4096
    unsigned b  = idx >> 17;                 // idx / (32*4096)

    int s = shifts[b] - MAX_SHIFT;           // [-409, 409]
    int src = (int)t - s;                    // [-409, 4504]
    if (src < 0)           src += T_DIM;
    else if (src >= T_DIM) src -= T_DIM;

    unsigned src_idx = (b << 17) + ((unsigned)src << 5) + c4;

    // Touch-once streams: evict-first reads + streaming store (the policy
    // PAIR is what wins; each alone is neutral-to-harmful).
    float4 xv = __ldcs(&x[src_idx]);
    float4 nv = __ldcs(&noise[src_idx]);

    float sc  = __ldg(&scale[b]);
    float nsc = sc * NOISE_STD;   // out = x*sc + n*(0.1*sc): independent MUL + FMA per lane

    float4 o;
    o.x = fmaf(nv.x, nsc, xv.x * sc);
    o.y = fmaf(nv.y, nsc, xv.y * sc);
    o.z = fmaf(nv.z, nsc, xv.z * sc);
    o.w = fmaf(nv.w, nsc, xv.w * sc);

    __stcs(&out[idx], o);
}

extern "C" void kernel_launch(void* const* d_in, const int* in_sizes, int n_in,
                              void* d_out, int out_size)
{
    const float4* x      = (const float4*)d_in[0];
    const float4* noise  = (const float4*)d_in[1];
    const float*  scale  = (const float*)d_in[2];
    const int*    shifts = (const int*)d_in[3];
    float4* out = (float4*)d_out;

    const unsigned total = B_DIM * T_DIM * C4;   // 8,388,608
    const unsigned blocks = total / THREADS;     // 32768

    ts_augment_kernel<<<blocks, THREADS>>>(x, noise, scale, shifts, out);
}